// round 4
// baseline (speedup 1.0000x reference)
#include <cuda_runtime.h>
#include <stdint.h>
#include <math.h>

#define Nn 50000
#define Ee 800000
#define Gg 16
#define Dd 64
#define Hh 128

// Scratch (allocation-free: __device__ globals)
__device__ float g_agg[Nn * Dd];     // attention-weighted edge aggregate per node
__device__ float g_nagg[Gg * Dd];    // node aggregate per graph
__device__ float g_eagg[Gg * Dd];    // edge aggregate per graph
__device__ float g_U1e[Gg * Hh];     // be1 + u @ We1[192:256]
__device__ float g_U1a[Gg * Hh];     // ba1 + u @ Wa1[192:256]
__device__ float g_U1n[Gg * Hh];     // bn1 + u @ Wn1[128:192]

// ---------------------------------------------------------------------------
// Packed fp32x2 helpers
// ---------------------------------------------------------------------------
__device__ __forceinline__ void fma2(uint64_t& d, uint64_t a, uint64_t b) {
    asm("fma.rn.f32x2 %0, %1, %2, %0;" : "+l"(d) : "l"(a), "l"(b));
}
__device__ __forceinline__ uint64_t rep2(float x) {
    uint64_t r; asm("mov.b64 %0, {%1, %1};" : "=l"(r) : "f"(x)); return r;
}
__device__ __forceinline__ float2 unpack2(uint64_t v) {
    float2 r; asm("mov.b64 {%0, %1}, %2;" : "=f"(r.x), "=f"(r.y) : "l"(v)); return r;
}
__device__ __forceinline__ void red4(float* p, float a, float b, float c, float d) {
    asm volatile("red.global.add.v4.f32 [%0], {%1,%2,%3,%4};"
                 :: "l"(p), "f"(a), "f"(b), "f"(c), "f"(d) : "memory");
}
__device__ __forceinline__ void cp16(float* smem_dst, const float* gsrc) {
    uint32_t s = (uint32_t)__cvta_generic_to_shared(smem_dst);
    asm volatile("cp.async.cg.shared.global [%0], [%1], 16;" :: "r"(s), "l"(gsrc));
}
__device__ __forceinline__ void cp_commit() { asm volatile("cp.async.commit_group;"); }
template<int N> __device__ __forceinline__ void cp_wait() {
    asm volatile("cp.async.wait_group %0;" :: "n"(N));
}

// ---------------------------------------------------------------------------
// W staging: GEMM1 tile = 32x128 (16KB), GEMM2 tile = 64x64 (16KB)
// ---------------------------------------------------------------------------
template<int NTH>
__device__ __forceinline__ void stage_w1(const float* __restrict__ Wg, int kt,
                                         float* __restrict__ dst, int t) {
    const float* src = Wg + (size_t)kt * 32 * 128;
#pragma unroll
    for (int i = 0; i < 1024 / NTH; i++) {
        int idx = t + i * NTH;
        int r = idx >> 5, c4 = (idx & 31) << 2;
        cp16(dst + r * 128 + c4, src + r * 128 + c4);
    }
}
template<int NTH>
__device__ __forceinline__ void stage_w2(const float* __restrict__ Wg, int kt,
                                         float* __restrict__ dst, int t) {
    const float* src = Wg + (size_t)kt * 64 * 64;
#pragma unroll
    for (int i = 0; i < 1024 / NTH; i++) {
        int idx = t + i * NTH;
        int r = idx >> 4, c4 = (idx & 15) << 2;
        cp16(dst + r * 64 + c4, src + r * 64 + c4);
    }
}

// ---------------------------------------------------------------------------
// GEMM1: Hs[128][MT] = relu(A^T @ W1 + U1[g]) ; A K-major, xor-swizzled.
// NTHREADS = 4*MT. tx: 8 cols, ty: 4 rows.
// ---------------------------------------------------------------------------
template<int KTOT, int MT>
__device__ __forceinline__ void gemm_h(const float* __restrict__ A,
                                       const float* __restrict__ Wg,
                                       const float* __restrict__ U1,
                                       const int* __restrict__ gidx,
                                       float* __restrict__ Hs,
                                       float* __restrict__ sW, int t)
{
    constexpr int NTH = MT * 4;
    constexpr int GM = MT / 4 - 1;
    const int tx = t & 15, ty = t >> 4;
    uint64_t acc[4][4];
#pragma unroll
    for (int i = 0; i < 4; i++) {
        int g = gidx[ty * 4 + i];
        const float* up = U1 + g * 128 + tx * 8;
#pragma unroll
        for (int p = 0; p < 4; p++) acc[i][p] = *(const uint64_t*)(up + p * 2);
    }
    constexpr int NT = KTOT / 32;
    stage_w1<NTH>(Wg, 0, sW, t);
    cp_commit();
#pragma unroll
    for (int kt = 0; kt < NT; kt++) {
        if (kt + 1 < NT) {
            stage_w1<NTH>(Wg, kt + 1, sW + ((kt + 1) & 1) * 4096, t);
            cp_commit();
            cp_wait<1>();
        } else cp_wait<0>();
        __syncthreads();
        const float* W = sW + (kt & 1) * 4096;
#pragma unroll
        for (int kk = 0; kk < 32; kk++) {
            int k = kt * 32 + kk;
            float4 a = *(const float4*)(A + k * MT + ((ty ^ ((k >> 2) & GM)) << 2));
            ulonglong2 w01 = *(const ulonglong2*)(W + kk * 128 + tx * 8);
            ulonglong2 w23 = *(const ulonglong2*)(W + kk * 128 + tx * 8 + 4);
            uint64_t a0 = rep2(a.x), a1 = rep2(a.y), a2 = rep2(a.z), a3 = rep2(a.w);
            fma2(acc[0][0], a0, w01.x); fma2(acc[0][1], a0, w01.y);
            fma2(acc[0][2], a0, w23.x); fma2(acc[0][3], a0, w23.y);
            fma2(acc[1][0], a1, w01.x); fma2(acc[1][1], a1, w01.y);
            fma2(acc[1][2], a1, w23.x); fma2(acc[1][3], a1, w23.y);
            fma2(acc[2][0], a2, w01.x); fma2(acc[2][1], a2, w01.y);
            fma2(acc[2][2], a2, w23.x); fma2(acc[2][3], a2, w23.y);
            fma2(acc[3][0], a3, w01.x); fma2(acc[3][1], a3, w01.y);
            fma2(acc[3][2], a3, w23.x); fma2(acc[3][3], a3, w23.y);
        }
        __syncthreads();
    }
#pragma unroll
    for (int i = 0; i < 4; i++)
#pragma unroll
        for (int p = 0; p < 4; p++) {
            float2 v = unpack2(acc[i][p]);
            int h0 = tx * 8 + p * 2;
            int c = ((ty ^ ((h0 >> 2) & GM)) << 2) | i;
            Hs[h0 * MT + c]       = fmaxf(v.x, 0.f);
            Hs[(h0 + 1) * MT + c] = fmaxf(v.y, 0.f);
        }
    __syncthreads();
}

// ---------------------------------------------------------------------------
// GEMM2: O[MT,64] = Hs^T @ W2 + b2. tx: 4 cols, ty: 4 rows.
// ---------------------------------------------------------------------------
template<int MT>
__device__ __forceinline__ void gemm_o(const float* __restrict__ Hs,
                                       const float* __restrict__ Wg,
                                       const float* __restrict__ b2,
                                       float* __restrict__ sW, int t,
                                       float o[4][4])
{
    constexpr int NTH = MT * 4;
    constexpr int GM = MT / 4 - 1;
    const int tx = t & 15, ty = t >> 4;
    uint64_t b0 = *(const uint64_t*)(b2 + tx * 4);
    uint64_t b1 = *(const uint64_t*)(b2 + tx * 4 + 2);
    uint64_t acc[4][2];
#pragma unroll
    for (int i = 0; i < 4; i++) { acc[i][0] = b0; acc[i][1] = b1; }
    stage_w2<NTH>(Wg, 0, sW, t);
    cp_commit();
#pragma unroll
    for (int kt = 0; kt < 2; kt++) {
        if (kt == 0) { stage_w2<NTH>(Wg, 1, sW + 4096, t); cp_commit(); cp_wait<1>(); }
        else cp_wait<0>();
        __syncthreads();
        const float* W = sW + kt * 4096;
#pragma unroll 8
        for (int kk = 0; kk < 64; kk++) {
            int k = kt * 64 + kk;
            float4 a = *(const float4*)(Hs + k * MT + ((ty ^ ((k >> 2) & GM)) << 2));
            ulonglong2 w = *(const ulonglong2*)(W + kk * 64 + tx * 4);
            uint64_t a0 = rep2(a.x), a1 = rep2(a.y), a2 = rep2(a.z), a3 = rep2(a.w);
            fma2(acc[0][0], a0, w.x); fma2(acc[0][1], a0, w.y);
            fma2(acc[1][0], a1, w.x); fma2(acc[1][1], a1, w.y);
            fma2(acc[2][0], a2, w.x); fma2(acc[2][1], a2, w.y);
            fma2(acc[3][0], a3, w.x); fma2(acc[3][1], a3, w.y);
        }
        __syncthreads();
    }
#pragma unroll
    for (int i = 0; i < 4; i++)
#pragma unroll
        for (int p = 0; p < 2; p++) {
            float2 v = unpack2(acc[i][p]);
            o[i][p * 2]     = v.x;
            o[i][p * 2 + 1] = v.y;
        }
}

// ---------------------------------------------------------------------------
// Edge kernel: 128 edges/CTA, 512 threads, 1 CTA/SM.
// smem floats: A[192*128]=24576 | sW[2*4096]=8192 | Hs[128*128]=16384 | idx 384
// ---------------------------------------------------------------------------
#define SME_A  0
#define SME_W  24576
#define SME_H  32768
#define SME_IX 49152
#define SME_FLOATS (49152 + 384)

__global__ void __launch_bounds__(512, 1)
edge_kernel(const float* __restrict__ x, const int* __restrict__ ei,
            const float* __restrict__ e, const int* __restrict__ batch,
            const float* __restrict__ We1, const float* __restrict__ We2,
            const float* __restrict__ be2,
            const float* __restrict__ Wa1, const float* __restrict__ Wa2,
            const float* __restrict__ ba2,
            float* __restrict__ e_out)
{
    extern __shared__ float smem[];
    float* A  = smem + SME_A;
    float* sW = smem + SME_W;
    float* Hs = smem + SME_H;
    int* srcs = (int*)(smem + SME_IX);
    int* dsts = srcs + 128;
    int* gidx = dsts + 128;
    const int t = threadIdx.x;
    const int eb = blockIdx.x * 128;

    if (t < 128) {
        int s_ = ei[eb + t], d_ = ei[Ee + eb + t];
        srcs[t] = s_; dsts[t] = d_; gidx[t] = batch[s_];
    }
    __syncthreads();

    // Build A = [xs | xd | e], K-major, xor-swizzled (32 float4-groups)
    for (int i = t; i < 2048; i += 512) {
        int m = i >> 4, k4 = (i & 15) << 2;
        int c1 = ((((m >> 2) ^ (k4 >> 2)) & 31) << 2) | (m & 3);           // rows k, 128+k
        int c2 = ((((m >> 2) ^ ((k4 >> 2) + 16)) & 31) << 2) | (m & 3);    // rows 64+k
        float4 v;
        v = *(const float4*)&x[(size_t)srcs[m] * 64 + k4];
        A[k4 * 128 + c1] = v.x; A[(k4 + 1) * 128 + c1] = v.y;
        A[(k4 + 2) * 128 + c1] = v.z; A[(k4 + 3) * 128 + c1] = v.w;
        v = *(const float4*)&x[(size_t)dsts[m] * 64 + k4];
        A[(64 + k4) * 128 + c2] = v.x; A[(64 + k4 + 1) * 128 + c2] = v.y;
        A[(64 + k4 + 2) * 128 + c2] = v.z; A[(64 + k4 + 3) * 128 + c2] = v.w;
        v = *(const float4*)&e[(size_t)(eb + m) * 64 + k4];
        A[(128 + k4) * 128 + c1] = v.x; A[(128 + k4 + 1) * 128 + c1] = v.y;
        A[(128 + k4 + 2) * 128 + c1] = v.z; A[(128 + k4 + 3) * 128 + c1] = v.w;
    }
    __syncthreads();

    const int tx = t & 15, ty = t >> 4;

    // e_new = MLP_e(A)
    gemm_h<192, 128>(A, We1, g_U1e, gidx, Hs, sW, t);
    float enew[4][4];
    gemm_o<128>(Hs, We2, be2, sW, t, enew);
    __syncthreads();                 // all Hs reads done; reuse Hs as eagg

    float* eagg = Hs;                // 16*64 floats overlay
    eagg[t] = 0.f; eagg[t + 512] = 0.f;
    __syncthreads();

    // write e_new; splice into A rows [128,192); accumulate per-graph sums
#pragma unroll
    for (int i = 0; i < 4; i++) {
        int row = ty * 4 + i;
        *(float4*)&e_out[(size_t)(eb + row) * 64 + tx * 4] =
            make_float4(enew[i][0], enew[i][1], enew[i][2], enew[i][3]);
        int cA = (((ty ^ tx) & 31) << 2) | i;   // rows 128+tx*4+j: (k>>2)&31 = tx
        int g = gidx[row];
#pragma unroll
        for (int j = 0; j < 4; j++) {
            A[(128 + tx * 4 + j) * 128 + cA] = enew[i][j];
            atomicAdd(&eagg[g * 64 + tx * 4 + j], enew[i][j]);
        }
    }
    __syncthreads();
    if (t < 256) {
        int g = t >> 4, c4 = (t & 15) << 2;
        const float* p = &eagg[g * 64 + c4];
        red4(&g_eagg[g * 64 + c4], p[0], p[1], p[2], p[3]);
    }

    // a = sigmoid(MLP_a(A with e_new))
    gemm_h<192, 128>(A, Wa1, g_U1a, gidx, Hs, sW, t);
    float av[4][4];
    gemm_o<128>(Hs, Wa2, ba2, sW, t, av);

    // scatter e_new * a into g_agg[dst]
#pragma unroll
    for (int i = 0; i < 4; i++) {
        int row = ty * 4 + i;
        int dst = dsts[row];
        float w0 = enew[i][0] / (1.f + __expf(-av[i][0]));
        float w1 = enew[i][1] / (1.f + __expf(-av[i][1]));
        float w2 = enew[i][2] / (1.f + __expf(-av[i][2]));
        float w3 = enew[i][3] / (1.f + __expf(-av[i][3]));
        red4(&g_agg[(size_t)dst * 64 + tx * 4], w0, w1, w2, w3);
    }
}

// ---------------------------------------------------------------------------
// Node kernel: 64 nodes/CTA, 256 threads, 2 CTAs/SM (unchanged config)
// ---------------------------------------------------------------------------
#define SMN_A  0
#define SMN_W  8192
#define SMN_H  16384
#define SMN_IX 24576
#define SMN_FLOATS (24576 + 64)

__global__ void __launch_bounds__(256, 2)
node_kernel(const float* __restrict__ x, const int* __restrict__ batch,
            const float* __restrict__ Wn1, const float* __restrict__ Wn2,
            const float* __restrict__ bn2,
            float* __restrict__ x_out)
{
    extern __shared__ float smem[];
    float* A  = smem + SMN_A;
    float* sW = smem + SMN_W;
    float* Hs = smem + SMN_H;
    int* gid  = (int*)(smem + SMN_IX);
    const int t = threadIdx.x;
    const int nb = blockIdx.x * 64;

    if (t < 64) {
        int r = nb + t; if (r >= Nn) r = Nn - 1;
        gid[t] = batch[r];
    }
    __syncthreads();

    for (int i = t; i < 1024; i += 256) {
        int m = i >> 4, k4 = (i & 15) << 2;
        int r = nb + m; if (r >= Nn) r = Nn - 1;
        int c = ((((m >> 2) ^ (k4 >> 2)) & 15) << 2) | (m & 3);
        float4 v;
        v = *(const float4*)&x[(size_t)r * 64 + k4];
        A[k4 * 64 + c] = v.x; A[(k4 + 1) * 64 + c] = v.y;
        A[(k4 + 2) * 64 + c] = v.z; A[(k4 + 3) * 64 + c] = v.w;
        v = *(const float4*)&g_agg[(size_t)r * 64 + k4];
        A[(64 + k4) * 64 + c] = v.x; A[(64 + k4 + 1) * 64 + c] = v.y;
        A[(64 + k4 + 2) * 64 + c] = v.z; A[(64 + k4 + 3) * 64 + c] = v.w;
    }
    __syncthreads();

    gemm_h<128, 64>(A, Wn1, g_U1n, gid, Hs, sW, t);
    float xo[4][4];
    gemm_o<64>(Hs, Wn2, bn2, sW, t, xo);
    __syncthreads();

    float* nagg = Hs;
#pragma unroll
    for (int i = 0; i < 4; i++) nagg[t + i * 256] = 0.f;
    __syncthreads();

    const int tx = t & 15, ty = t >> 4;
#pragma unroll
    for (int i = 0; i < 4; i++) {
        int row = ty * 4 + i;
        int r = nb + row;
        if (r < Nn) {
            *(float4*)&x_out[(size_t)r * 64 + tx * 4] =
                make_float4(xo[i][0], xo[i][1], xo[i][2], xo[i][3]);
            int g = gid[row];
#pragma unroll
            for (int j = 0; j < 4; j++)
                atomicAdd(&nagg[g * 64 + tx * 4 + j], xo[i][j]);
        }
    }
    __syncthreads();
    {
        int g = t >> 4, c4 = (t & 15) << 2;
        const float* p = &nagg[g * 64 + c4];
        red4(&g_nagg[g * 64 + c4], p[0], p[1], p[2], p[3]);
    }
}

// ---------------------------------------------------------------------------
// Global kernel: 16 blocks x 128 threads
// ---------------------------------------------------------------------------
__global__ void __launch_bounds__(128)
global_kernel(const float* __restrict__ u,
              const float* __restrict__ Wg1, const float* __restrict__ bg1,
              const float* __restrict__ Wg2, const float* __restrict__ bg2,
              float* __restrict__ u_out)
{
    __shared__ float in[192];
    __shared__ float hid[128];
    const int g = blockIdx.x, t = threadIdx.x;
    if (t < 64) {
        in[t]       = u[g * 64 + t];
        in[64 + t]  = g_nagg[g * 64 + t];
        in[128 + t] = g_eagg[g * 64 + t];
    }
    __syncthreads();
    float acc = bg1[t];
#pragma unroll 8
    for (int k = 0; k < 192; k++) acc += in[k] * Wg1[(size_t)k * 128 + t];
    hid[t] = fmaxf(acc, 0.f);
    __syncthreads();
    if (t < 64) {
        float a2 = bg2[t];
#pragma unroll 8
        for (int k = 0; k < 128; k++) a2 += hid[k] * Wg2[(size_t)k * 64 + t];
        u_out[g * 64 + t] = a2;
    }
}

// ---------------------------------------------------------------------------
// Prep kernel: zero aggregates + precompute U1 tables (bias folded)
// ---------------------------------------------------------------------------
__global__ void __launch_bounds__(256)
prep_kernel(const float* __restrict__ u,
            const float* __restrict__ We1, const float* __restrict__ be1,
            const float* __restrict__ Wa1, const float* __restrict__ ba1,
            const float* __restrict__ Wn1, const float* __restrict__ bn1)
{
    const int b = blockIdx.x, t = threadIdx.x;
    size_t idx = (size_t)b * 256 + t;
    const size_t n4 = (size_t)Nn * Dd / 4;
    float4 z = make_float4(0.f, 0.f, 0.f, 0.f);
    for (size_t i = idx; i < n4; i += (size_t)gridDim.x * 256) ((float4*)g_agg)[i] = z;
    if (idx < 256) { ((float4*)g_nagg)[idx] = z; ((float4*)g_eagg)[idx] = z; }
    if (b < 3) {
        const float* W    = (b == 0) ? We1 + 192 * 128 : (b == 1) ? Wa1 + 192 * 128 : Wn1 + 128 * 128;
        const float* bias = (b == 0) ? be1 : (b == 1) ? ba1 : bn1;
        float* out        = (b == 0) ? g_U1e : (b == 1) ? g_U1a : g_U1n;
        for (int i = t; i < Gg * Hh; i += 256) {
            int g = i >> 7, h = i & 127;
            float acc = bias[h];
#pragma unroll 8
            for (int k = 0; k < 64; k++) acc += u[g * 64 + k] * W[(size_t)k * 128 + h];
            out[i] = acc;
        }
    }
}

extern "C" void kernel_launch(void* const* d_in, const int* in_sizes, int n_in,
                              void* d_out, int out_size)
{
    const float* x     = (const float*)d_in[0];
    const int*   ei    = (const int*)d_in[1];
    const float* e     = (const float*)d_in[2];
    const float* u     = (const float*)d_in[3];
    const int*   batch = (const int*)d_in[4];
    const float* We1 = (const float*)d_in[5];
    const float* be1 = (const float*)d_in[6];
    const float* We2 = (const float*)d_in[7];
    const float* be2 = (const float*)d_in[8];
    const float* Wa1 = (const float*)d_in[9];
    const float* ba1 = (const float*)d_in[10];
    const float* Wa2 = (const float*)d_in[11];
    const float* ba2 = (const float*)d_in[12];
    const float* Wn1 = (const float*)d_in[13];
    const float* bn1 = (const float*)d_in[14];
    const float* Wn2 = (const float*)d_in[15];
    const float* bn2 = (const float*)d_in[16];
    const float* Wg1 = (const float*)d_in[17];
    const float* bg1 = (const float*)d_in[18];
    const float* Wg2 = (const float*)d_in[19];
    const float* bg2 = (const float*)d_in[20];

    float* out   = (float*)d_out;
    float* x_out = out;
    float* e_out = out + (size_t)Nn * Dd;
    float* u_out = out + (size_t)Nn * Dd + (size_t)Ee * Dd;

    cudaFuncSetAttribute(edge_kernel, cudaFuncAttributeMaxDynamicSharedMemorySize,
                         SME_FLOATS * 4);
    cudaFuncSetAttribute(node_kernel, cudaFuncAttributeMaxDynamicSharedMemorySize,
                         SMN_FLOATS * 4);

    prep_kernel<<<3125, 256>>>(u, We1, be1, Wa1, ba1, Wn1, bn1);
    edge_kernel<<<Ee / 128, 512, SME_FLOATS * 4>>>(x, ei, e, batch,
                                                   We1, We2, be2, Wa1, Wa2, ba2, e_out);
    node_kernel<<<(Nn + 63) / 64, 256, SMN_FLOATS * 4>>>(x, batch, Wn1, Wn2, bn2, x_out);
    global_kernel<<<Gg, 128>>>(u, Wg1, bg1, Wg2, bg2, u_out);
}

// round 5
// speedup vs baseline: 1.7076x; 1.7076x over previous
#include <cuda_runtime.h>
#include <stdint.h>
#include <math.h>

#define Nn 50000
#define Ee 800000
#define Gg 16
#define Dd 64
#define Hh 128

// Scratch (allocation-free: __device__ globals)
__device__ float g_agg[Nn * Dd];      // attention-weighted edge aggregate per node
__device__ float g_nagg[Gg * Dd];     // node aggregate per graph
__device__ float g_eagg[Gg * Dd];     // edge aggregate per graph
__device__ float g_U1e[Gg * Hh];      // be1 + u @ We1[192:256]
__device__ float g_U1a[Gg * Hh];      // ba1 + u @ Wa1[192:256]
__device__ float g_U1n[Gg * Hh];      // bn1 + u @ Wn1[128:192]
__device__ float g_Xs[(size_t)Nn * 256];  // [x@We1[0:64] | x@Wa1[0:64]]
__device__ float g_Xd[(size_t)Nn * 256];  // [x@We1[64:128] | x@Wa1[64:128]]
__device__ float g_Xn[(size_t)Nn * 128];  // x@Wn1[0:64]

// ---------------------------------------------------------------------------
// Packed fp32x2 helpers
// ---------------------------------------------------------------------------
__device__ __forceinline__ void fma2(uint64_t& d, uint64_t a, uint64_t b) {
    asm("fma.rn.f32x2 %0, %1, %2, %0;" : "+l"(d) : "l"(a), "l"(b));
}
__device__ __forceinline__ uint64_t add2(uint64_t a, uint64_t b) {
    uint64_t r; asm("add.rn.f32x2 %0, %1, %2;" : "=l"(r) : "l"(a), "l"(b)); return r;
}
__device__ __forceinline__ uint64_t rep2(float x) {
    uint64_t r; asm("mov.b64 %0, {%1, %1};" : "=l"(r) : "f"(x)); return r;
}
__device__ __forceinline__ float2 unpack2(uint64_t v) {
    float2 r; asm("mov.b64 {%0, %1}, %2;" : "=f"(r.x), "=f"(r.y) : "l"(v)); return r;
}
__device__ __forceinline__ void red4(float* p, float a, float b, float c, float d) {
    asm volatile("red.global.add.v4.f32 [%0], {%1,%2,%3,%4};"
                 :: "l"(p), "f"(a), "f"(b), "f"(c), "f"(d) : "memory");
}
__device__ __forceinline__ void cp16(float* smem_dst, const float* gsrc) {
    uint32_t s = (uint32_t)__cvta_generic_to_shared(smem_dst);
    asm volatile("cp.async.cg.shared.global [%0], [%1], 16;" :: "r"(s), "l"(gsrc));
}
__device__ __forceinline__ void cp_commit() { asm volatile("cp.async.commit_group;"); }
template<int N> __device__ __forceinline__ void cp_wait() {
    asm volatile("cp.async.wait_group %0;" :: "n"(N));
}

// ---------------------------------------------------------------------------
// W staging: GEMM1 tile = 32x128 (16KB), GEMM2 tile = 64x64 (16KB)
// ---------------------------------------------------------------------------
__device__ __forceinline__ void stage_w1(const float* __restrict__ Wg, int kt,
                                         float* __restrict__ dst, int t) {
    const float* src = Wg + (size_t)kt * 32 * 128;
#pragma unroll
    for (int i = 0; i < 4; i++) {
        int idx = t + i * 256;
        int r = idx >> 5, c4 = (idx & 31) << 2;
        cp16(dst + r * 128 + c4, src + r * 128 + c4);
    }
}
__device__ __forceinline__ void stage_w2(const float* __restrict__ Wg, int kt,
                                         float* __restrict__ dst, int t) {
    const float* src = Wg + (size_t)kt * 64 * 64;
#pragma unroll
    for (int i = 0; i < 4; i++) {
        int idx = t + i * 256;
        int r = idx >> 4, c4 = (idx & 15) << 2;
        cp16(dst + r * 64 + c4, src + r * 64 + c4);
    }
}

// ---------------------------------------------------------------------------
// GEMM1: Hs[128][64] = relu(A^T @ W1 + ini) ; A K-major, xor-swizzled.
// 256 threads: tx 8 cols, ty 4 rows. ini = precomputed accumulator init.
// ---------------------------------------------------------------------------
template<int KTOT>
__device__ __forceinline__ void gemm_h(const float* __restrict__ A,
                                       const float* __restrict__ Wg,
                                       const uint64_t (&ini)[4][4],
                                       float* __restrict__ Hs,
                                       float* __restrict__ sW, int t)
{
    const int tx = t & 15, ty = t >> 4;
    uint64_t acc[4][4];
#pragma unroll
    for (int i = 0; i < 4; i++)
#pragma unroll
        for (int p = 0; p < 4; p++) acc[i][p] = ini[i][p];
    constexpr int NT = KTOT / 32;
    stage_w1(Wg, 0, sW, t);
    cp_commit();
#pragma unroll
    for (int kt = 0; kt < NT; kt++) {
        if (kt + 1 < NT) {
            stage_w1(Wg, kt + 1, sW + ((kt + 1) & 1) * 4096, t);
            cp_commit();
            cp_wait<1>();
        } else cp_wait<0>();
        __syncthreads();
        const float* W = sW + (kt & 1) * 4096;
#pragma unroll
        for (int kk = 0; kk < 32; kk++) {
            int k = kt * 32 + kk;
            float4 a = *(const float4*)(A + k * 64 + ((ty ^ ((k >> 2) & 15)) << 2));
            ulonglong2 w01 = *(const ulonglong2*)(W + kk * 128 + tx * 8);
            ulonglong2 w23 = *(const ulonglong2*)(W + kk * 128 + tx * 8 + 4);
            uint64_t a0 = rep2(a.x), a1 = rep2(a.y), a2 = rep2(a.z), a3 = rep2(a.w);
            fma2(acc[0][0], a0, w01.x); fma2(acc[0][1], a0, w01.y);
            fma2(acc[0][2], a0, w23.x); fma2(acc[0][3], a0, w23.y);
            fma2(acc[1][0], a1, w01.x); fma2(acc[1][1], a1, w01.y);
            fma2(acc[1][2], a1, w23.x); fma2(acc[1][3], a1, w23.y);
            fma2(acc[2][0], a2, w01.x); fma2(acc[2][1], a2, w01.y);
            fma2(acc[2][2], a2, w23.x); fma2(acc[2][3], a2, w23.y);
            fma2(acc[3][0], a3, w01.x); fma2(acc[3][1], a3, w01.y);
            fma2(acc[3][2], a3, w23.x); fma2(acc[3][3], a3, w23.y);
        }
        __syncthreads();
    }
#pragma unroll
    for (int i = 0; i < 4; i++)
#pragma unroll
        for (int p = 0; p < 4; p++) {
            float2 v = unpack2(acc[i][p]);
            int h0 = tx * 8 + p * 2;
            int c = ((ty ^ ((h0 >> 2) & 15)) << 2) | i;
            Hs[h0 * 64 + c]       = fmaxf(v.x, 0.f);
            Hs[(h0 + 1) * 64 + c] = fmaxf(v.y, 0.f);
        }
    __syncthreads();
}

// ---------------------------------------------------------------------------
// GEMM2: O[64,64] = Hs^T @ W2 + b2. tx: 4 cols, ty: 4 rows.
// ---------------------------------------------------------------------------
__device__ __forceinline__ void gemm_o(const float* __restrict__ Hs,
                                       const float* __restrict__ Wg,
                                       const float* __restrict__ b2,
                                       float* __restrict__ sW, int t,
                                       float o[4][4])
{
    const int tx = t & 15, ty = t >> 4;
    uint64_t b0 = *(const uint64_t*)(b2 + tx * 4);
    uint64_t b1 = *(const uint64_t*)(b2 + tx * 4 + 2);
    uint64_t acc[4][2];
#pragma unroll
    for (int i = 0; i < 4; i++) { acc[i][0] = b0; acc[i][1] = b1; }
    stage_w2(Wg, 0, sW, t);
    cp_commit();
#pragma unroll
    for (int kt = 0; kt < 2; kt++) {
        if (kt == 0) { stage_w2(Wg, 1, sW + 4096, t); cp_commit(); cp_wait<1>(); }
        else cp_wait<0>();
        __syncthreads();
        const float* W = sW + kt * 4096;
#pragma unroll 8
        for (int kk = 0; kk < 64; kk++) {
            int k = kt * 64 + kk;
            float4 a = *(const float4*)(Hs + k * 64 + ((ty ^ ((k >> 2) & 15)) << 2));
            ulonglong2 w = *(const ulonglong2*)(W + kk * 64 + tx * 4);
            uint64_t a0 = rep2(a.x), a1 = rep2(a.y), a2 = rep2(a.z), a3 = rep2(a.w);
            fma2(acc[0][0], a0, w.x); fma2(acc[0][1], a0, w.y);
            fma2(acc[1][0], a1, w.x); fma2(acc[1][1], a1, w.y);
            fma2(acc[2][0], a2, w.x); fma2(acc[2][1], a2, w.y);
            fma2(acc[3][0], a3, w.x); fma2(acc[3][1], a3, w.y);
        }
        __syncthreads();
    }
#pragma unroll
    for (int i = 0; i < 4; i++)
#pragma unroll
        for (int p = 0; p < 2; p++) {
            float2 v = unpack2(acc[i][p]);
            o[i][p * 2]     = v.x;
            o[i][p * 2 + 1] = v.y;
        }
}

// ---------------------------------------------------------------------------
// Edge kernel: 64 edges/CTA, 256 threads, 2 CTAs/SM. A = e only (K=64).
// GEMM1 acc init = U1[g] + Xs[src] + Xd[dst]  (precomputed node tables).
// smem floats: A[64*64]=4096 | sW[2*4096]=8192 | Hs[128*64]=8192 | idx 192
// ---------------------------------------------------------------------------
#define SME_A  0
#define SME_W  4096
#define SME_H  12288
#define SME_IX 20480
#define SME_FLOATS (20480 + 192)

__global__ void __launch_bounds__(256, 2)
edge_kernel(const int* __restrict__ ei,
            const float* __restrict__ e, const int* __restrict__ batch,
            const float* __restrict__ We1, const float* __restrict__ We2,
            const float* __restrict__ be2,
            const float* __restrict__ Wa1, const float* __restrict__ Wa2,
            const float* __restrict__ ba2,
            float* __restrict__ e_out)
{
    extern __shared__ float smem[];
    float* A  = smem + SME_A;
    float* sW = smem + SME_W;
    float* Hs = smem + SME_H;
    int* srcs = (int*)(smem + SME_IX);
    int* dsts = srcs + 64;
    int* gidx = dsts + 64;
    const int t = threadIdx.x;
    const int eb = blockIdx.x * 64;

    if (t < 64) {
        int s_ = ei[eb + t], d_ = ei[Ee + eb + t];
        srcs[t] = s_; dsts[t] = d_; gidx[t] = batch[s_];
    }
    __syncthreads();

    // Build A = e tile, K-major, xor-swizzled
    for (int i = t; i < 1024; i += 256) {
        int m = i >> 4, k4 = (i & 15) << 2;
        int c = ((((m >> 2) ^ (k4 >> 2)) & 15) << 2) | (m & 3);
        float4 v = *(const float4*)&e[(size_t)(eb + m) * 64 + k4];
        A[k4 * 64 + c] = v.x; A[(k4 + 1) * 64 + c] = v.y;
        A[(k4 + 2) * 64 + c] = v.z; A[(k4 + 3) * 64 + c] = v.w;
    }
    __syncthreads();

    const int tx = t & 15, ty = t >> 4;

    // --- MLP_e: acc init from gathered tables, then K=64 GEMM on e ---
    uint64_t ini[4][4];
#pragma unroll
    for (int i = 0; i < 4; i++) {
        int row = ty * 4 + i;
        const float* up = g_U1e + gidx[row] * 128 + tx * 8;
        const float* xs = g_Xs + (size_t)srcs[row] * 256 + tx * 8;
        const float* xd = g_Xd + (size_t)dsts[row] * 256 + tx * 8;
#pragma unroll
        for (int p = 0; p < 4; p++)
            ini[i][p] = add2(*(const uint64_t*)(up + p * 2),
                        add2(*(const uint64_t*)(xs + p * 2),
                             *(const uint64_t*)(xd + p * 2)));
    }
    gemm_h<64>(A, We1 + 128 * 128, ini, Hs, sW, t);
    float enew[4][4];
    gemm_o(Hs, We2, be2, sW, t, enew);
    __syncthreads();                 // all Hs reads done; reuse Hs as eagg

    float* eagg = Hs;                // 16*64 floats overlay
#pragma unroll
    for (int i = 0; i < 4; i++) eagg[t + i * 256] = 0.f;
    __syncthreads();

    // write e_new; splice into A; accumulate per-graph sums
#pragma unroll
    for (int i = 0; i < 4; i++) {
        int row = ty * 4 + i;
        *(float4*)&e_out[(size_t)(eb + row) * 64 + tx * 4] =
            make_float4(enew[i][0], enew[i][1], enew[i][2], enew[i][3]);
        int cA = (((ty ^ tx) & 15) << 2) | i;
        int g = gidx[row];
#pragma unroll
        for (int j = 0; j < 4; j++) {
            A[(tx * 4 + j) * 64 + cA] = enew[i][j];
            atomicAdd(&eagg[g * 64 + tx * 4 + j], enew[i][j]);
        }
    }
    __syncthreads();
    {
        int g = t >> 4, c4 = (t & 15) << 2;
        const float* p = &eagg[g * 64 + c4];
        red4(&g_eagg[g * 64 + c4], p[0], p[1], p[2], p[3]);
    }

    // --- MLP_a: same structure, second half of tables ---
#pragma unroll
    for (int i = 0; i < 4; i++) {
        int row = ty * 4 + i;
        const float* up = g_U1a + gidx[row] * 128 + tx * 8;
        const float* xs = g_Xs + (size_t)srcs[row] * 256 + 128 + tx * 8;
        const float* xd = g_Xd + (size_t)dsts[row] * 256 + 128 + tx * 8;
#pragma unroll
        for (int p = 0; p < 4; p++)
            ini[i][p] = add2(*(const uint64_t*)(up + p * 2),
                        add2(*(const uint64_t*)(xs + p * 2),
                             *(const uint64_t*)(xd + p * 2)));
    }
    gemm_h<64>(A, Wa1 + 128 * 128, ini, Hs, sW, t);
    float av[4][4];
    gemm_o(Hs, Wa2, ba2, sW, t, av);

    // scatter e_new * sigmoid(a) into g_agg[dst]
#pragma unroll
    for (int i = 0; i < 4; i++) {
        int row = ty * 4 + i;
        int dst = dsts[row];
        float w0 = enew[i][0] / (1.f + __expf(-av[i][0]));
        float w1 = enew[i][1] / (1.f + __expf(-av[i][1]));
        float w2 = enew[i][2] / (1.f + __expf(-av[i][2]));
        float w3 = enew[i][3] / (1.f + __expf(-av[i][3]));
        red4(&g_agg[(size_t)dst * 64 + tx * 4], w0, w1, w2, w3);
    }
}

// ---------------------------------------------------------------------------
// Node kernel: 64 nodes/CTA. A = agg only (K=64); init = U1n[g] + Xn[node].
// ---------------------------------------------------------------------------
#define SMN_A  0
#define SMN_W  4096
#define SMN_H  12288
#define SMN_IX 20480
#define SMN_FLOATS (20480 + 64)

__global__ void __launch_bounds__(256, 2)
node_kernel(const int* __restrict__ batch,
            const float* __restrict__ Wn1, const float* __restrict__ Wn2,
            const float* __restrict__ bn2,
            float* __restrict__ x_out)
{
    extern __shared__ float smem[];
    float* A  = smem + SMN_A;
    float* sW = smem + SMN_W;
    float* Hs = smem + SMN_H;
    int* gid  = (int*)(smem + SMN_IX);
    const int t = threadIdx.x;
    const int nb = blockIdx.x * 64;

    if (t < 64) {
        int r = nb + t; if (r >= Nn) r = Nn - 1;
        gid[t] = batch[r];
    }
    __syncthreads();

    for (int i = t; i < 1024; i += 256) {
        int m = i >> 4, k4 = (i & 15) << 2;
        int r = nb + m; if (r >= Nn) r = Nn - 1;
        int c = ((((m >> 2) ^ (k4 >> 2)) & 15) << 2) | (m & 3);
        float4 v = *(const float4*)&g_agg[(size_t)r * 64 + k4];
        A[k4 * 64 + c] = v.x; A[(k4 + 1) * 64 + c] = v.y;
        A[(k4 + 2) * 64 + c] = v.z; A[(k4 + 3) * 64 + c] = v.w;
    }
    __syncthreads();

    const int tx = t & 15, ty = t >> 4;
    uint64_t ini[4][4];
#pragma unroll
    for (int i = 0; i < 4; i++) {
        int row = ty * 4 + i;
        int r = nb + row; if (r >= Nn) r = Nn - 1;
        const float* up = g_U1n + gid[row] * 128 + tx * 8;
        const float* xn = g_Xn + (size_t)r * 128 + tx * 8;
#pragma unroll
        for (int p = 0; p < 4; p++)
            ini[i][p] = add2(*(const uint64_t*)(up + p * 2),
                             *(const uint64_t*)(xn + p * 2));
    }
    gemm_h<64>(A, Wn1 + 64 * 128, ini, Hs, sW, t);
    float xo[4][4];
    gemm_o(Hs, Wn2, bn2, sW, t, xo);
    __syncthreads();

    float* nagg = Hs;
#pragma unroll
    for (int i = 0; i < 4; i++) nagg[t + i * 256] = 0.f;
    __syncthreads();

#pragma unroll
    for (int i = 0; i < 4; i++) {
        int row = ty * 4 + i;
        int r = nb + row;
        if (r < Nn) {
            *(float4*)&x_out[(size_t)r * 64 + tx * 4] =
                make_float4(xo[i][0], xo[i][1], xo[i][2], xo[i][3]);
            int g = gid[row];
#pragma unroll
            for (int j = 0; j < 4; j++)
                atomicAdd(&nagg[g * 64 + tx * 4 + j], xo[i][j]);
        }
    }
    __syncthreads();
    {
        int g = t >> 4, c4 = (t & 15) << 2;
        const float* p = &nagg[g * 64 + c4];
        red4(&g_nagg[g * 64 + c4], p[0], p[1], p[2], p[3]);
    }
}

// ---------------------------------------------------------------------------
// Prep tables: per 64-node tile, load x once, emit 5 x (64x128) GEMM outputs
// into g_Xs / g_Xd / g_Xn.
// ---------------------------------------------------------------------------
#define SPT_FLOATS 12288

__global__ void __launch_bounds__(256, 2)
prep_tables(const float* __restrict__ x,
            const float* __restrict__ We1, const float* __restrict__ Wa1,
            const float* __restrict__ Wn1)
{
    extern __shared__ float smem[];
    float* A  = smem;
    float* sW = smem + 4096;
    const int t = threadIdx.x;
    const int nb = blockIdx.x * 64;
    const int tx = t & 15, ty = t >> 4;

    for (int i = t; i < 1024; i += 256) {
        int m = i >> 4, k4 = (i & 15) << 2;
        int r = nb + m; if (r >= Nn) r = Nn - 1;
        int c = ((((m >> 2) ^ (k4 >> 2)) & 15) << 2) | (m & 3);
        float4 v = *(const float4*)&x[(size_t)r * 64 + k4];
        A[k4 * 64 + c] = v.x; A[(k4 + 1) * 64 + c] = v.y;
        A[(k4 + 2) * 64 + c] = v.z; A[(k4 + 3) * 64 + c] = v.w;
    }
    __syncthreads();

    const float* Ws[5] = { We1, Wa1, We1 + 64 * 128, Wa1 + 64 * 128, Wn1 };
    float* outs[5] = { g_Xs, g_Xs + 128, g_Xd, g_Xd + 128, g_Xn };
    const int stride[5] = { 256, 256, 256, 256, 128 };

#pragma unroll 1
    for (int seg = 0; seg < 5; seg++) {
        const float* W = Ws[seg];
        stage_w1(W, 0, sW, t);
        stage_w1(W, 1, sW + 4096, t);
        cp_commit();
        cp_wait<0>();
        __syncthreads();
        uint64_t acc[4][4];
#pragma unroll
        for (int i = 0; i < 4; i++)
#pragma unroll
            for (int p = 0; p < 4; p++) acc[i][p] = 0ull;
#pragma unroll
        for (int kt = 0; kt < 2; kt++) {
            const float* Wp = sW + kt * 4096;
#pragma unroll
            for (int kk = 0; kk < 32; kk++) {
                int k = kt * 32 + kk;
                float4 a = *(const float4*)(A + k * 64 + ((ty ^ ((k >> 2) & 15)) << 2));
                ulonglong2 w01 = *(const ulonglong2*)(Wp + kk * 128 + tx * 8);
                ulonglong2 w23 = *(const ulonglong2*)(Wp + kk * 128 + tx * 8 + 4);
                uint64_t a0 = rep2(a.x), a1 = rep2(a.y), a2 = rep2(a.z), a3 = rep2(a.w);
                fma2(acc[0][0], a0, w01.x); fma2(acc[0][1], a0, w01.y);
                fma2(acc[0][2], a0, w23.x); fma2(acc[0][3], a0, w23.y);
                fma2(acc[1][0], a1, w01.x); fma2(acc[1][1], a1, w01.y);
                fma2(acc[1][2], a1, w23.x); fma2(acc[1][3], a1, w23.y);
                fma2(acc[2][0], a2, w01.x); fma2(acc[2][1], a2, w01.y);
                fma2(acc[2][2], a2, w23.x); fma2(acc[2][3], a2, w23.y);
                fma2(acc[3][0], a3, w01.x); fma2(acc[3][1], a3, w01.y);
                fma2(acc[3][2], a3, w23.x); fma2(acc[3][3], a3, w23.y);
            }
        }
        // store 4 rows x 8 cols
#pragma unroll
        for (int i = 0; i < 4; i++) {
            int r = nb + ty * 4 + i;
            if (r < Nn) {
                float* op = outs[seg] + (size_t)r * stride[seg] + tx * 8;
                float2 v0 = unpack2(acc[i][0]), v1 = unpack2(acc[i][1]);
                float2 v2 = unpack2(acc[i][2]), v3 = unpack2(acc[i][3]);
                *(float4*)op       = make_float4(v0.x, v0.y, v1.x, v1.y);
                *(float4*)(op + 4) = make_float4(v2.x, v2.y, v3.x, v3.y);
            }
        }
        __syncthreads();   // sW reuse fence
    }
}

// ---------------------------------------------------------------------------
// Global kernel: 16 blocks x 128 threads
// ---------------------------------------------------------------------------
__global__ void __launch_bounds__(128)
global_kernel(const float* __restrict__ u,
              const float* __restrict__ Wg1, const float* __restrict__ bg1,
              const float* __restrict__ Wg2, const float* __restrict__ bg2,
              float* __restrict__ u_out)
{
    __shared__ float in[192];
    __shared__ float hid[128];
    const int g = blockIdx.x, t = threadIdx.x;
    if (t < 64) {
        in[t]       = u[g * 64 + t];
        in[64 + t]  = g_nagg[g * 64 + t];
        in[128 + t] = g_eagg[g * 64 + t];
    }
    __syncthreads();
    float acc = bg1[t];
#pragma unroll 8
    for (int k = 0; k < 192; k++) acc += in[k] * Wg1[(size_t)k * 128 + t];
    hid[t] = fmaxf(acc, 0.f);
    __syncthreads();
    if (t < 64) {
        float a2 = bg2[t];
#pragma unroll 8
        for (int k = 0; k < 128; k++) a2 += hid[k] * Wg2[(size_t)k * 64 + t];
        u_out[g * 64 + t] = a2;
    }
}

// ---------------------------------------------------------------------------
// Prep kernel: zero aggregates + precompute U1 tables (bias folded)
// ---------------------------------------------------------------------------
__global__ void __launch_bounds__(256)
prep_kernel(const float* __restrict__ u,
            const float* __restrict__ We1, const float* __restrict__ be1,
            const float* __restrict__ Wa1, const float* __restrict__ ba1,
            const float* __restrict__ Wn1, const float* __restrict__ bn1)
{
    const int b = blockIdx.x, t = threadIdx.x;
    size_t idx = (size_t)b * 256 + t;
    const size_t n4 = (size_t)Nn * Dd / 4;
    float4 z = make_float4(0.f, 0.f, 0.f, 0.f);
    for (size_t i = idx; i < n4; i += (size_t)gridDim.x * 256) ((float4*)g_agg)[i] = z;
    if (idx < 256) { ((float4*)g_nagg)[idx] = z; ((float4*)g_eagg)[idx] = z; }
    if (b < 3) {
        const float* W    = (b == 0) ? We1 + 192 * 128 : (b == 1) ? Wa1 + 192 * 128 : Wn1 + 128 * 128;
        const float* bias = (b == 0) ? be1 : (b == 1) ? ba1 : bn1;
        float* out        = (b == 0) ? g_U1e : (b == 1) ? g_U1a : g_U1n;
        for (int i = t; i < Gg * Hh; i += 256) {
            int g = i >> 7, h = i & 127;
            float acc = bias[h];
#pragma unroll 8
            for (int k = 0; k < 64; k++) acc += u[g * 64 + k] * W[(size_t)k * 128 + h];
            out[i] = acc;
        }
    }
}

extern "C" void kernel_launch(void* const* d_in, const int* in_sizes, int n_in,
                              void* d_out, int out_size)
{
    const float* x     = (const float*)d_in[0];
    const int*   ei    = (const int*)d_in[1];
    const float* e     = (const float*)d_in[2];
    const float* u     = (const float*)d_in[3];
    const int*   batch = (const int*)d_in[4];
    const float* We1 = (const float*)d_in[5];
    const float* be1 = (const float*)d_in[6];
    const float* We2 = (const float*)d_in[7];
    const float* be2 = (const float*)d_in[8];
    const float* Wa1 = (const float*)d_in[9];
    const float* ba1 = (const float*)d_in[10];
    const float* Wa2 = (const float*)d_in[11];
    const float* ba2 = (const float*)d_in[12];
    const float* Wn1 = (const float*)d_in[13];
    const float* bn1 = (const float*)d_in[14];
    const float* Wn2 = (const float*)d_in[15];
    const float* bn2 = (const float*)d_in[16];
    const float* Wg1 = (const float*)d_in[17];
    const float* bg1 = (const float*)d_in[18];
    const float* Wg2 = (const float*)d_in[19];
    const float* bg2 = (const float*)d_in[20];

    float* out   = (float*)d_out;
    float* x_out = out;
    float* e_out = out + (size_t)Nn * Dd;
    float* u_out = out + (size_t)Nn * Dd + (size_t)Ee * Dd;

    cudaFuncSetAttribute(edge_kernel, cudaFuncAttributeMaxDynamicSharedMemorySize,
                         SME_FLOATS * 4);
    cudaFuncSetAttribute(node_kernel, cudaFuncAttributeMaxDynamicSharedMemorySize,
                         SMN_FLOATS * 4);
    cudaFuncSetAttribute(prep_tables, cudaFuncAttributeMaxDynamicSharedMemorySize,
                         SPT_FLOATS * 4);

    prep_kernel<<<3125, 256>>>(u, We1, be1, Wa1, ba1, Wn1, bn1);
    prep_tables<<<(Nn + 63) / 64, 256, SPT_FLOATS * 4>>>(x, We1, Wa1, Wn1);
    edge_kernel<<<Ee / 64, 256, SME_FLOATS * 4>>>(ei, e, batch,
                                                  We1, We2, be2, Wa1, Wa2, ba2, e_out);
    node_kernel<<<(Nn + 63) / 64, 256, SMN_FLOATS * 4>>>(batch, Wn1, Wn2, bn2, x_out);
    global_kernel<<<Gg, 128>>>(u, Wg1, bg1, Wg2, bg2, u_out);
}